// round 14
// baseline (speedup 1.0000x reference)
#include <cuda_runtime.h>

#define BB 4
#define CC 64
#define HH 256
#define WW 256
#define HWN 65536
#define HO 130
#define NCHUNK 32

typedef unsigned long long ull;

// ---------------- scratch (device globals; no allocations) ----------------
__device__ float g_qrgb[BB*CC*HWN];
__device__ float g_s  [4][BB*CC*HO*HO];
__device__ float g_cvt0[BB*2*CC*HWN];
__device__ float g_cvt1[BB*2*CC*HWN];
__device__ float g_kvr[BB*2*CC*HWN];
__device__ float g_kvd[BB*2*CC*HWN];
__device__ float g_part[2][32][NCHUNK][80];
__device__ float g_attn[2][32][64];

// db3 filters
__constant__ float c_DEC_LO[6] = { 0.035226291882100656f, -0.08544127388224149f, -0.13501102001039084f,
                                   0.4598775021193313f,    0.8068915093133388f,   0.3326705529509569f };
__constant__ float c_DEC_HI[6] = {-0.3326705529509569f,    0.8068915093133388f,  -0.4598775021193313f,
                                  -0.13501102001039084f,   0.08544127388224149f,  0.035226291882100656f };
__constant__ float c_REC_LO[6] = { 0.3326705529509569f,    0.8068915093133388f,   0.4598775021193313f,
                                  -0.13501102001039084f,  -0.08544127388224149f,  0.035226291882100656f };
__constant__ float c_REC_HI[6] = { 0.035226291882100656f,  0.08544127388224149f, -0.13501102001039084f,
                                  -0.4598775021193313f,    0.8068915093133388f,  -0.3326705529509569f };

// ---------------- packed f32x2 helpers ----------------
__device__ __forceinline__ ull pk(float lo, float hi) {
    ull r;
    asm("mov.b64 %0, {%1, %2};" : "=l"(r) : "r"(__float_as_uint(lo)), "r"(__float_as_uint(hi)));
    return r;
}
__device__ __forceinline__ void upk(float& lo, float& hi, ull v) {
    unsigned a, b;
    asm("mov.b64 {%0, %1}, %2;" : "=r"(a), "=r"(b) : "l"(v));
    lo = __uint_as_float(a); hi = __uint_as_float(b);
}
__device__ __forceinline__ void ffma2(ull& d, ull a, ull b) {
    asm("fma.rn.f32x2 %0, %1, %2, %0;" : "+l"(d) : "l"(a), "l"(b));
}
__device__ __forceinline__ ull fmul2(ull a, ull b) {
    ull r; asm("mul.rn.f32x2 %0, %1, %2;" : "=l"(r) : "l"(a), "l"(b)); return r;
}

// ================= fused DWT (rows+cols): rgb -> 4 subbands =================
__global__ __launch_bounds__(256) void mfe_front_k(const float* __restrict__ x) {
    __shared__ float sLo[36*130], sHi[36*130];
    int bc = blockIdx.y;
    int i0 = blockIdx.x * 16;
    int iCnt = min(16, HO - i0);
    int rbase = max(0, 2*i0 - 4);
    int rend  = min(HH-1, 2*(i0 + iCnt - 1) + 1);
    int nR = rend - rbase + 1;
    const float* plane = x + ((size_t)bc << 16);

    for (int idx = threadIdx.x; idx < nR*130; idx += 256) {
        int rl = idx / 130, j = idx - rl*130;
        const float* row = plane + ((rbase + rl) << 8);
        float lo = 0.f, hi = 0.f;
        int base = 2*j - 4;
        #pragma unroll
        for (int s = 0; s < 6; s++) {
            int col = base + s;
            if (col >= 0 && col < WW) {
                float v = row[col];
                lo += v * c_REC_LO[s];
                hi += v * c_REC_HI[s];
            }
        }
        sLo[idx] = lo; sHi[idx] = hi;
    }
    __syncthreads();

    size_t obase = (size_t)bc * (HO*HO);
    for (int idx = threadIdx.x; idx < iCnt*130; idx += 256) {
        int il = idx / 130, xc = idx - il*130;
        int i = i0 + il;
        float ll=0.f, lh=0.f, hl=0.f, hh=0.f;
        int rb = 2*i - 4;
        #pragma unroll
        for (int t = 0; t < 6; t++) {
            int r = rb + t;
            if (r >= 0 && r < HH) {
                int rl = r - rbase;
                float vl = sLo[rl*130 + xc], vh = sHi[rl*130 + xc];
                ll += vl*c_REC_LO[t]; lh += vl*c_REC_HI[t];
                hl += vh*c_REC_LO[t]; hh += vh*c_REC_HI[t];
            }
        }
        size_t o = obase + (size_t)i*HO + xc;
        g_s[0][o]=ll; g_s[1][o]=lh; g_s[2][o]=hl; g_s[3][o]=hh;
    }
}

// ======= fused dw3(subbands) + IDWT(cols+rows): 4 subbands -> qrgb =======
#define RAW_W 134
#define RAW_ROWS 12
#define RAW_SB (RAW_ROWS*RAW_W)          // 1608
#define POST_SB (10*130)                 // 1300
__global__ __launch_bounds__(256) void mfe_back_k(const float* __restrict__ w1, const float* __restrict__ w5,
                                                  const float* __restrict__ w7, const float* __restrict__ w9) {
    extern __shared__ float sdyn[];
    float* sRaw  = sdyn;
    float* sPost = sdyn + 4*RAW_SB;
    __shared__ float sW[36];

    int bc = blockIdx.y;
    int c  = bc & 63;
    int m0 = blockIdx.x * 16;
    int jp0 = m0 >> 1;
    int warp = threadIdx.x >> 5, lane = threadIdx.x & 31;

    if (threadIdx.x < 36) {
        int s = threadIdx.x / 9, k = threadIdx.x - s*9;
        const float* wp = (s==0) ? w1 : (s==1) ? w5 : (s==2) ? w7 : w9;
        sW[threadIdx.x] = wp[c*9 + k];
    }

    size_t sbase = (size_t)bc * (HO*HO);
    #pragma unroll
    for (int s = 0; s < 4; s++) {
        const float* sb = g_s[s] + sbase;
        float* rawb = sRaw + s*RAW_SB;
        for (int rl = warp; rl < RAW_ROWS; rl += 8) {
            int jg = jp0 - 1 + rl;
            bool ok = (jg >= 0) && (jg < HO);
            const float2* src = (const float2*)(sb + (size_t)jg*HO);
            float* dst = rawb + rl*RAW_W;
            for (int x2 = lane; x2 < 65; x2 += 32) {
                float2 v = ok ? src[x2] : make_float2(0.f, 0.f);
                *(float2*)(dst + 2 + 2*x2) = v;
            }
            if (lane == 0) { dst[1] = 0.f; dst[132] = 0.f; }
        }
    }
    __syncthreads();

    for (int task = warp; task < 40; task += 8) {
        int s = task / 10, pl = task - s*10;
        const float* wr = sW + s*9;
        float k0 = wr[0], k1 = wr[1], k2 = wr[2],
              k3 = wr[3], k4 = wr[4], k5 = wr[5],
              k6 = wr[6], k7 = wr[7], k8 = wr[8];
        const float* r0 = sRaw + s*RAW_SB + pl*RAW_W + 2;
        const float* r1 = r0 + RAW_W;
        const float* r2 = r1 + RAW_W;
        float* pb = sPost + s*POST_SB + pl*130;
        for (int xc = lane; xc < 130; xc += 32) {
            float acc = k0*r0[xc-1] + k1*r0[xc] + k2*r0[xc+1]
                      + k3*r1[xc-1] + k4*r1[xc] + k5*r1[xc+1]
                      + k6*r2[xc-1] + k7*r2[xc] + k8*r2[xc+1];
            pb[xc] = acc;
        }
    }
    __syncthreads();

    float* sL2 = sdyn;
    float* sH2 = sdyn + 2080;
    for (int ml = warp; ml < 16; ml += 8) {
        int m = m0 + ml;
        int i0f = (m & 1) ? 0 : 1;
        int jl = ml >> 1;
        float dl0 = c_DEC_LO[i0f],   dh0 = c_DEC_HI[i0f];
        float dl1 = c_DEC_LO[i0f+2], dh1 = c_DEC_HI[i0f+2];
        float dl2 = c_DEC_LO[i0f+4], dh2 = c_DEC_HI[i0f+4];
        const float* p0 = sPost + 0*POST_SB + jl*130;
        const float* p1 = sPost + 1*POST_SB + jl*130;
        const float* p2 = sPost + 2*POST_SB + jl*130;
        const float* p3 = sPost + 3*POST_SB + jl*130;
        float* l2 = sL2 + ml*130;
        float* h2 = sH2 + ml*130;
        for (int xc = lane; xc < 130; xc += 32) {
            float lo = p0[xc]*dl0 + p1[xc]*dh0
                     + p0[xc+130]*dl1 + p1[xc+130]*dh1
                     + p0[xc+260]*dl2 + p1[xc+260]*dh2;
            float hi = p2[xc]*dl0 + p3[xc]*dh0
                     + p2[xc+130]*dl1 + p3[xc+130]*dh1
                     + p2[xc+260]*dl2 + p3[xc+260]*dh2;
            l2[xc] = lo; h2[xc] = hi;
        }
    }
    __syncthreads();

    float DL0 = c_DEC_LO[0], DL1 = c_DEC_LO[1], DL2 = c_DEC_LO[2],
          DL3 = c_DEC_LO[3], DL4 = c_DEC_LO[4], DL5 = c_DEC_LO[5];
    float DH0 = c_DEC_HI[0], DH1 = c_DEC_HI[1], DH2 = c_DEC_HI[2],
          DH3 = c_DEC_HI[3], DH4 = c_DEC_HI[4], DH5 = c_DEC_HI[5];
    float* oplane = g_qrgb + ((size_t)bc << 16);
    for (int ml = warp; ml < 16; ml += 8) {
        const float* lrow = sL2 + ml*130;
        const float* hrow = sH2 + ml*130;
        float* orow = oplane + ((m0 + ml) << 8);
        for (int wp = lane; wp < 128; wp += 32) {
            float a  = lrow[wp], b  = lrow[wp+1], cc = lrow[wp+2];
            float ha = hrow[wp], hb = hrow[wp+1], hc = hrow[wp+2];
            float even = a*DL1 + b*DL3 + cc*DL5 + ha*DH1 + hb*DH3 + hc*DH5;
            float odd  = a*DL0 + b*DL2 + cc*DL4 + ha*DH0 + hb*DH2 + hc*DH4;
            *(float2*)(orow + 2*wp) = make_float2(even, odd);
        }
    }
}

// ======== 1x1 conv 64->128: both halves in smem, 4 passes x 32 outs, 2 px/thread ========
__global__ __launch_bounds__(256) void conv1x1_k(const float* __restrict__ in,
                                                 const float* __restrict__ w,
                                                 float* __restrict__ out) {
    extern __shared__ ull swT[];   // [c][o] packed, all 128 outputs: 64KB
    for (int i = threadIdx.x; i < 8192; i += 256) {
        int c = i >> 7, o = i & 127;
        float wv = w[o*64 + c];
        swT[i] = pk(wv, wv);
    }
    __syncthreads();
    int b = blockIdx.y;
    int pb = (blockIdx.x*256 + threadIdx.x)*2;
    const float* ib = in  + (size_t)b*CC*HWN + pb;
    float*       ob = out + (size_t)b*(2*CC)*HWN + pb;

    #pragma unroll 1
    for (int pass = 0; pass < 4; pass++) {
        ull acc[32];
        #pragma unroll
        for (int o = 0; o < 32; o++) acc[o] = 0ULL;
        #pragma unroll 4
        for (int c = 0; c < 64; c++) {
            float2 x = *(const float2*)(ib + (size_t)c*HWN);
            ull xx = pk(x.x, x.y);
            const ulonglong2* wr = (const ulonglong2*)(swT + (c << 7) + (pass << 5));
            #pragma unroll
            for (int o2 = 0; o2 < 16; o2++) {
                ulonglong2 wv = wr[o2];          // LDS.128 broadcast: 2 outputs
                ffma2(acc[2*o2],   wv.x, xx);
                ffma2(acc[2*o2+1], wv.y, xx);
            }
        }
        #pragma unroll
        for (int o = 0; o < 32; o++) {
            float2 r; upk(r.x, r.y, acc[o]);
            *(float2*)(ob + (size_t)(pass*32 + o)*HWN) = r;
        }
    }
}

// ======== depthwise 3x3, shuffle edges, 8 px/thread, rolling rows ========
struct Row8 {
    float4 A, B;
    float pw, nx;
};
__device__ __forceinline__ Row8 load_row8(const float* plane, int y, int lane) {
    Row8 r;
    if (y < 0 || y >= HH) {
        r.A = make_float4(0.f,0.f,0.f,0.f);
        r.B = r.A; r.pw = 0.f; r.nx = 0.f;
        float pw = __shfl_up_sync(0xffffffffu, 0.f, 1);
        float nx = __shfl_down_sync(0xffffffffu, 0.f, 1);
        (void)pw; (void)nx;
        return r;
    }
    const float* p = plane + (y << 8) + (lane << 3);
    r.A = *(const float4*)p;
    r.B = *(const float4*)(p + 4);
    float pw = __shfl_up_sync(0xffffffffu, r.B.w, 1);
    float nx = __shfl_down_sync(0xffffffffu, r.A.x, 1);
    r.pw = (lane == 0)  ? 0.f : pw;
    r.nx = (lane == 31) ? 0.f : nx;
    return r;
}
__device__ __forceinline__ void acc_row8(float* acc, const Row8& r, float wa, float wb, float wc) {
    acc[0] += wa*r.pw  + wb*r.A.x + wc*r.A.y;
    acc[1] += wa*r.A.x + wb*r.A.y + wc*r.A.z;
    acc[2] += wa*r.A.y + wb*r.A.z + wc*r.A.w;
    acc[3] += wa*r.A.z + wb*r.A.w + wc*r.B.x;
    acc[4] += wa*r.A.w + wb*r.B.x + wc*r.B.y;
    acc[5] += wa*r.B.x + wb*r.B.y + wc*r.B.z;
    acc[6] += wa*r.B.y + wb*r.B.z + wc*r.B.w;
    acc[7] += wa*r.B.z + wb*r.B.w + wc*r.nx;
}

__global__ __launch_bounds__(256) void dw3_k(const float* __restrict__ in,
                                             const float* __restrict__ wt,
                                             float* __restrict__ out) {
    int bc = blockIdx.y;
    int c  = bc & 127;
    int warp = threadIdx.x >> 5, lane = threadIdx.x & 31;
    int yb = blockIdx.x*64 + warp*8;

    float w[9];
    #pragma unroll
    for (int k = 0; k < 9; k++) w[k] = wt[c*9 + k];

    const float* plane = in  + ((size_t)bc << 16);
    float*      oplane = out + ((size_t)bc << 16);

    Row8 rp = load_row8(plane, yb - 1, lane);
    Row8 rc = load_row8(plane, yb,     lane);
    #pragma unroll
    for (int i = 0; i < 8; i++) {
        Row8 rn = load_row8(plane, yb + i + 1, lane);
        float acc[8];
        #pragma unroll
        for (int k = 0; k < 8; k++) acc[k] = 0.f;
        acc_row8(acc, rp, w[0], w[1], w[2]);
        acc_row8(acc, rc, w[3], w[4], w[5]);
        acc_row8(acc, rn, w[6], w[7], w[8]);
        float* op = oplane + ((yb + i) << 8) + (lane << 3);
        *(float4*)op       = make_float4(acc[0], acc[1], acc[2], acc[3]);
        *(float4*)(op + 4) = make_float4(acc[4], acc[5], acc[6], acc[7]);
        rp = rc; rc = rn;
    }
}

// ---------- Gram reduction, single modality (runs inside each branch) ----------
__global__ __launch_bounds__(256) void reduce_qk_k(const float* __restrict__ q,
                                                   const float* __restrict__ kv, int which) {
    int chunk = blockIdx.x;
    int bh    = blockIdx.y;
    int b = bh >> 3, h = bh & 7;
    size_t qoff = ((size_t)b*64  + h*8)*HWN;
    size_t koff = ((size_t)b*128 + h*8)*HWN;

    float acc[64]; float qn[8]; float kn[8];
    #pragma unroll
    for (int i = 0; i < 64; i++) acc[i] = 0.f;
    #pragma unroll
    for (int i = 0; i < 8; i++) { qn[i] = 0.f; kn[i] = 0.f; }

    const int CS4 = HWN / NCHUNK / 4;    // 512
    int start = chunk * CS4;
    for (int it = threadIdx.x; it < CS4; it += blockDim.x) {
        int idx = start + it;
        float4 qv[8];
        #pragma unroll
        for (int c = 0; c < 8; c++) {
            qv[c] = ((const float4*)(q + qoff + (size_t)c*HWN))[idx];
            qn[c] += qv[c].x*qv[c].x + qv[c].y*qv[c].y + qv[c].z*qv[c].z + qv[c].w*qv[c].w;
        }
        #pragma unroll
        for (int d = 0; d < 8; d++) {
            float4 k4 = ((const float4*)(kv + koff + (size_t)d*HWN))[idx];
            kn[d] += k4.x*k4.x + k4.y*k4.y + k4.z*k4.z + k4.w*k4.w;
            #pragma unroll
            for (int c = 0; c < 8; c++)
                acc[d*8+c] += qv[c].x*k4.x + qv[c].y*k4.y + qv[c].z*k4.z + qv[c].w*k4.w;
        }
    }

    __shared__ float sm[8][80];
    int lane = threadIdx.x & 31, warp = threadIdx.x >> 5;
    #pragma unroll
    for (int v = 0; v < 64; v++) {
        float r = acc[v];
        for (int s = 16; s > 0; s >>= 1) r += __shfl_down_sync(0xffffffffu, r, s);
        if (lane == 0) sm[warp][v] = r;
    }
    #pragma unroll
    for (int v = 0; v < 8; v++) {
        float r = qn[v];
        for (int s = 16; s > 0; s >>= 1) r += __shfl_down_sync(0xffffffffu, r, s);
        if (lane == 0) sm[warp][64+v] = r;
        float r2 = kn[v];
        for (int s = 16; s > 0; s >>= 1) r2 += __shfl_down_sync(0xffffffffu, r2, s);
        if (lane == 0) sm[warp][72+v] = r2;
    }
    __syncthreads();
    if (threadIdx.x < 80) {
        float s = 0.f;
        #pragma unroll
        for (int wg = 0; wg < 8; wg++) s += sm[wg][threadIdx.x];
        g_part[which][bh][chunk][threadIdx.x] = s;
    }
}

// ---------------- finish reduction + softmax ----------------
__global__ void attn_k(const float* __restrict__ temp) {
    int which = blockIdx.x >> 5;
    int bh    = blockIdx.x & 31;
    int h     = bh & 7;
    __shared__ float sm[80];
    if (threadIdx.x < 80) {
        float s = 0.f;
        #pragma unroll
        for (int ch = 0; ch < NCHUNK; ch++) s += g_part[which][bh][ch][threadIdx.x];
        sm[threadIdx.x] = s;
    }
    __syncthreads();
    if (threadIdx.x < 8) {
        int c = threadIdx.x;
        float t  = temp[h];
        float nq = fmaxf(sqrtf(sm[64+c]), 1e-12f);
        float srow[8];
        #pragma unroll
        for (int d = 0; d < 8; d++) {
            float nk = fmaxf(sqrtf(sm[72+d]), 1e-12f);
            float s = sm[d*8+c] / nk;
            if (which == 0) s /= nq;
            srow[d] = s * t;
        }
        float mx = srow[0];
        #pragma unroll
        for (int d = 1; d < 8; d++) mx = fmaxf(mx, srow[d]);
        float sum = 0.f;
        #pragma unroll
        for (int d = 0; d < 8; d++) { srow[d] = __expf(srow[d]-mx); sum += srow[d]; }
        float inv = 1.f / sum;
        #pragma unroll
        for (int d = 0; d < 8; d++) g_attn[which][bh][c*8+d] = srow[d]*inv;
    }
}

// ---------------- fused epilogue (f32x2, 2 px/thread, LDS.128 pairs) ----------------
__global__ __launch_bounds__(256) void final_k(const float* __restrict__ wproj,
                                               float* __restrict__ out) {
    __shared__ ull sA1t[512], sA2t[512];
    __shared__ ull sW[4096];
    int b = blockIdx.y;
    for (int i = threadIdx.x; i < 512; i += 256) {
        int h = i >> 6, d = (i >> 3) & 7, c = i & 7;
        float a1 = g_attn[0][b*8 + h][c*8 + d];
        float a2 = g_attn[1][b*8 + h][c*8 + d];
        sA1t[i] = pk(a1, a1);
        sA2t[i] = pk(a2, a2);
    }
    for (int i = threadIdx.x; i < 4096; i += 256) {
        float wv = wproj[i];
        sW[i] = pk(wv, wv);
    }
    __syncthreads();

    int n = (blockIdx.x*256 + threadIdx.x)*2;
    const float* vr = g_kvr + ((size_t)b*128 + 64)*HWN + n;
    const float* vd = g_kvd + ((size_t)b*128 + 64)*HWN + n;

    ull p[64];
    #pragma unroll 1
    for (int h = 0; h < 8; h++) {
        ull os[8], oc[8];
        #pragma unroll
        for (int c = 0; c < 8; c++) { os[c] = 0ULL; oc[c] = 0ULL; }
        #pragma unroll
        for (int d = 0; d < 8; d++) {
            float2 r2 = *(const float2*)(vr + (size_t)(h*8+d)*HWN);
            float2 d2 = *(const float2*)(vd + (size_t)(h*8+d)*HWN);
            ull rr = pk(r2.x, r2.y);
            ull dd = pk(d2.x, d2.y);
            const ulonglong2* a1p = (const ulonglong2*)(sA1t + h*64 + d*8);
            const ulonglong2* a2p = (const ulonglong2*)(sA2t + h*64 + d*8);
            #pragma unroll
            for (int c2 = 0; c2 < 4; c2++) {
                ulonglong2 w1 = a1p[c2];
                ffma2(os[2*c2],   w1.x, rr);
                ffma2(os[2*c2+1], w1.y, rr);
                ulonglong2 w2 = a2p[c2];
                ffma2(oc[2*c2],   w2.x, dd);
                ffma2(oc[2*c2+1], w2.y, dd);
            }
        }
        #pragma unroll
        for (int c = 0; c < 8; c++) p[h*8+c] = fmul2(os[c], oc[c]);
    }

    float* ob = out + (size_t)b*64*HWN + n;
    #pragma unroll 4
    for (int o = 0; o < 64; o++) {
        ull acc = 0ULL;
        const ulonglong2* wr = (const ulonglong2*)(sW + o*64);
        #pragma unroll
        for (int c2 = 0; c2 < 32; c2++) {
            ulonglong2 wv = wr[c2];
            ffma2(acc, wv.x, p[2*c2]);
            ffma2(acc, wv.y, p[2*c2+1]);
        }
        float2 r; upk(r.x, r.y, acc);
        *(float2*)(ob + (size_t)o*HWN) = r;
    }
}

// ---------------- host launch ----------------
extern "C" void kernel_launch(void* const* d_in, const int* in_sizes, int n_in,
                              void* d_out, int out_size) {
    const float* rgb   = (const float*)d_in[0];
    const float* depth = (const float*)d_in[1];
    const float* temp  = (const float*)d_in[2];
    const float* wqr   = (const float*)d_in[3];
    const float* wqd   = (const float*)d_in[4];
    const float* wqc   = (const float*)d_in[5];
    const float* w1    = (const float*)d_in[6];
    const float* w5    = (const float*)d_in[7];
    const float* w7    = (const float*)d_in[8];
    const float* w9    = (const float*)d_in[9];
    const float* wproj = (const float*)d_in[10];
    float* out = (float*)d_out;

    void* p;
    cudaGetSymbolAddress(&p, g_qrgb); float* qrg  = (float*)p;
    cudaGetSymbolAddress(&p, g_cvt0); float* cvt0 = (float*)p;
    cudaGetSymbolAddress(&p, g_cvt1); float* cvt1 = (float*)p;
    cudaGetSymbolAddress(&p, g_kvr);  float* kvr  = (float*)p;
    cudaGetSymbolAddress(&p, g_kvd);  float* kvd  = (float*)p;

    static cudaStream_t s1 = 0, s2 = 0;
    static cudaEvent_t evFork1 = 0, evFork2 = 0, evMfe = 0, evRedD = 0;
    if (!s1) {
        cudaStreamCreateWithFlags(&s1, cudaStreamNonBlocking);
        cudaStreamCreateWithFlags(&s2, cudaStreamNonBlocking);
        cudaEventCreateWithFlags(&evFork1, cudaEventDisableTiming);
        cudaEventCreateWithFlags(&evFork2, cudaEventDisableTiming);
        cudaEventCreateWithFlags(&evMfe,  cudaEventDisableTiming);
        cudaEventCreateWithFlags(&evRedD, cudaEventDisableTiming);
    }

    const int T = 256;
    const int MFE_BACK_SMEM = (4*RAW_SB + 4*POST_SB) * 4;   // 46528 B
    const int CONV_SMEM = 64*128*8;                          // 65536 B
    cudaFuncSetAttribute(mfe_back_k, cudaFuncAttributeMaxDynamicSharedMemorySize, MFE_BACK_SMEM);
    cudaFuncSetAttribute(conv1x1_k,  cudaFuncAttributeMaxDynamicSharedMemorySize, CONV_SMEM);

    // fork: main(0) -> s1 (mfe), s2 (depth chain)
    cudaEventRecord(evFork1, 0);
    cudaStreamWaitEvent(s1, evFork1, 0);
    cudaEventRecord(evFork2, 0);
    cudaStreamWaitEvent(s2, evFork2, 0);

    dim3 cg(HWN/(T*2), BB);        // 128 x 4 blocks, 2 px/thread
    dim3 dg(4, BB*128);
    dim3 rg(NCHUNK, 32);

    // ---- branch s1: MFE ----
    dim3 fgk(9, BB*CC);
    mfe_front_k<<<fgk, T, 0, s1>>>(rgb);
    dim3 bgk(16, BB*CC);
    mfe_back_k<<<bgk, T, MFE_BACK_SMEM, s1>>>(w1, w5, w7, w9);
    cudaEventRecord(evMfe, s1);

    // ---- branch s2: depth conv -> dw3 -> reduce_d (after mfe) ----
    conv1x1_k<<<cg, T, CONV_SMEM, s2>>>(depth, wqd, cvt1);
    dw3_k<<<dg, T, 0, s2>>>(cvt1, wqc, kvd);
    cudaStreamWaitEvent(s2, evMfe, 0);
    reduce_qk_k<<<rg, T, 0, s2>>>(qrg, kvd, 1);
    cudaEventRecord(evRedD, s2);

    // ---- main stream: rgb conv -> dw3 -> reduce_r (after mfe) ----
    conv1x1_k<<<cg, T, CONV_SMEM>>>(rgb, wqr, cvt0);
    dw3_k<<<dg, T>>>(cvt0, wqc, kvr);
    cudaStreamWaitEvent(0, evMfe, 0);
    reduce_qk_k<<<rg, T>>>(qrg, kvr, 0);

    // join depth branch, then softmax + epilogue
    cudaStreamWaitEvent(0, evRedD, 0);
    attn_k<<<64, 128>>>(temp);

    dim3 fg(HWN/(T*2), BB);
    final_k<<<fg, T>>>(wproj, out);
}

// round 15
// speedup vs baseline: 1.1573x; 1.1573x over previous
#include <cuda_runtime.h>

#define BB 4
#define CC 64
#define HH 256
#define WW 256
#define HWN 65536
#define HO 130
#define NCHUNK 32

typedef unsigned long long ull;

// ---------------- scratch (device globals; no allocations) ----------------
__device__ float g_qrgb[BB*CC*HWN];
__device__ float g_s  [4][BB*CC*HO*HO];
__device__ float g_cvt0[BB*2*CC*HWN];
__device__ float g_cvt1[BB*2*CC*HWN];
__device__ float g_kvr[BB*2*CC*HWN];
__device__ float g_kvd[BB*2*CC*HWN];
__device__ float g_part[2][32][NCHUNK][80];
__device__ float g_attn[2][32][64];

// db3 filters
__constant__ float c_DEC_LO[6] = { 0.035226291882100656f, -0.08544127388224149f, -0.13501102001039084f,
                                   0.4598775021193313f,    0.8068915093133388f,   0.3326705529509569f };
__constant__ float c_DEC_HI[6] = {-0.3326705529509569f,    0.8068915093133388f,  -0.4598775021193313f,
                                  -0.13501102001039084f,   0.08544127388224149f,  0.035226291882100656f };
__constant__ float c_REC_LO[6] = { 0.3326705529509569f,    0.8068915093133388f,   0.4598775021193313f,
                                  -0.13501102001039084f,  -0.08544127388224149f,  0.035226291882100656f };
__constant__ float c_REC_HI[6] = { 0.035226291882100656f,  0.08544127388224149f, -0.13501102001039084f,
                                  -0.4598775021193313f,    0.8068915093133388f,  -0.3326705529509569f };

// ---------------- packed f32x2 helpers ----------------
__device__ __forceinline__ ull pk(float lo, float hi) {
    ull r;
    asm("mov.b64 %0, {%1, %2};" : "=l"(r) : "r"(__float_as_uint(lo)), "r"(__float_as_uint(hi)));
    return r;
}
__device__ __forceinline__ void upk(float& lo, float& hi, ull v) {
    unsigned a, b;
    asm("mov.b64 {%0, %1}, %2;" : "=r"(a), "=r"(b) : "l"(v));
    lo = __uint_as_float(a); hi = __uint_as_float(b);
}
__device__ __forceinline__ void ffma2(ull& d, ull a, ull b) {
    asm("fma.rn.f32x2 %0, %1, %2, %0;" : "+l"(d) : "l"(a), "l"(b));
}
__device__ __forceinline__ ull fmul2(ull a, ull b) {
    ull r; asm("mul.rn.f32x2 %0, %1, %2;" : "=l"(r) : "l"(a), "l"(b)); return r;
}

// ================= fused DWT (rows+cols): rgb -> 4 subbands =================
__global__ __launch_bounds__(256) void mfe_front_k(const float* __restrict__ x) {
    __shared__ float sLo[36*130], sHi[36*130];
    int bc = blockIdx.y;
    int i0 = blockIdx.x * 16;
    int iCnt = min(16, HO - i0);
    int rbase = max(0, 2*i0 - 4);
    int rend  = min(HH-1, 2*(i0 + iCnt - 1) + 1);
    int nR = rend - rbase + 1;
    const float* plane = x + ((size_t)bc << 16);

    for (int idx = threadIdx.x; idx < nR*130; idx += 256) {
        int rl = idx / 130, j = idx - rl*130;
        const float* row = plane + ((rbase + rl) << 8);
        float lo = 0.f, hi = 0.f;
        int base = 2*j - 4;
        #pragma unroll
        for (int s = 0; s < 6; s++) {
            int col = base + s;
            if (col >= 0 && col < WW) {
                float v = row[col];
                lo += v * c_REC_LO[s];
                hi += v * c_REC_HI[s];
            }
        }
        sLo[idx] = lo; sHi[idx] = hi;
    }
    __syncthreads();

    size_t obase = (size_t)bc * (HO*HO);
    for (int idx = threadIdx.x; idx < iCnt*130; idx += 256) {
        int il = idx / 130, xc = idx - il*130;
        int i = i0 + il;
        float ll=0.f, lh=0.f, hl=0.f, hh=0.f;
        int rb = 2*i - 4;
        #pragma unroll
        for (int t = 0; t < 6; t++) {
            int r = rb + t;
            if (r >= 0 && r < HH) {
                int rl = r - rbase;
                float vl = sLo[rl*130 + xc], vh = sHi[rl*130 + xc];
                ll += vl*c_REC_LO[t]; lh += vl*c_REC_HI[t];
                hl += vh*c_REC_LO[t]; hh += vh*c_REC_HI[t];
            }
        }
        size_t o = obase + (size_t)i*HO + xc;
        g_s[0][o]=ll; g_s[1][o]=lh; g_s[2][o]=hl; g_s[3][o]=hh;
    }
}

// ======= fused dw3(subbands) + IDWT(cols+rows): 4 subbands -> qrgb =======
#define RAW_W 134
#define RAW_ROWS 12
#define RAW_SB (RAW_ROWS*RAW_W)          // 1608
#define POST_SB (10*130)                 // 1300
__global__ __launch_bounds__(256) void mfe_back_k(const float* __restrict__ w1, const float* __restrict__ w5,
                                                  const float* __restrict__ w7, const float* __restrict__ w9) {
    extern __shared__ float sdyn[];
    float* sRaw  = sdyn;
    float* sPost = sdyn + 4*RAW_SB;
    __shared__ float sW[36];

    int bc = blockIdx.y;
    int c  = bc & 63;
    int m0 = blockIdx.x * 16;
    int jp0 = m0 >> 1;
    int warp = threadIdx.x >> 5, lane = threadIdx.x & 31;

    if (threadIdx.x < 36) {
        int s = threadIdx.x / 9, k = threadIdx.x - s*9;
        const float* wp = (s==0) ? w1 : (s==1) ? w5 : (s==2) ? w7 : w9;
        sW[threadIdx.x] = wp[c*9 + k];
    }

    size_t sbase = (size_t)bc * (HO*HO);
    #pragma unroll
    for (int s = 0; s < 4; s++) {
        const float* sb = g_s[s] + sbase;
        float* rawb = sRaw + s*RAW_SB;
        for (int rl = warp; rl < RAW_ROWS; rl += 8) {
            int jg = jp0 - 1 + rl;
            bool ok = (jg >= 0) && (jg < HO);
            const float2* src = (const float2*)(sb + (size_t)jg*HO);
            float* dst = rawb + rl*RAW_W;
            for (int x2 = lane; x2 < 65; x2 += 32) {
                float2 v = ok ? src[x2] : make_float2(0.f, 0.f);
                *(float2*)(dst + 2 + 2*x2) = v;
            }
            if (lane == 0) { dst[1] = 0.f; dst[132] = 0.f; }
        }
    }
    __syncthreads();

    for (int task = warp; task < 40; task += 8) {
        int s = task / 10, pl = task - s*10;
        const float* wr = sW + s*9;
        float k0 = wr[0], k1 = wr[1], k2 = wr[2],
              k3 = wr[3], k4 = wr[4], k5 = wr[5],
              k6 = wr[6], k7 = wr[7], k8 = wr[8];
        const float* r0 = sRaw + s*RAW_SB + pl*RAW_W + 2;
        const float* r1 = r0 + RAW_W;
        const float* r2 = r1 + RAW_W;
        float* pb = sPost + s*POST_SB + pl*130;
        for (int xc = lane; xc < 130; xc += 32) {
            float acc = k0*r0[xc-1] + k1*r0[xc] + k2*r0[xc+1]
                      + k3*r1[xc-1] + k4*r1[xc] + k5*r1[xc+1]
                      + k6*r2[xc-1] + k7*r2[xc] + k8*r2[xc+1];
            pb[xc] = acc;
        }
    }
    __syncthreads();

    float* sL2 = sdyn;
    float* sH2 = sdyn + 2080;
    for (int ml = warp; ml < 16; ml += 8) {
        int m = m0 + ml;
        int i0f = (m & 1) ? 0 : 1;
        int jl = ml >> 1;
        float dl0 = c_DEC_LO[i0f],   dh0 = c_DEC_HI[i0f];
        float dl1 = c_DEC_LO[i0f+2], dh1 = c_DEC_HI[i0f+2];
        float dl2 = c_DEC_LO[i0f+4], dh2 = c_DEC_HI[i0f+4];
        const float* p0 = sPost + 0*POST_SB + jl*130;
        const float* p1 = sPost + 1*POST_SB + jl*130;
        const float* p2 = sPost + 2*POST_SB + jl*130;
        const float* p3 = sPost + 3*POST_SB + jl*130;
        float* l2 = sL2 + ml*130;
        float* h2 = sH2 + ml*130;
        for (int xc = lane; xc < 130; xc += 32) {
            float lo = p0[xc]*dl0 + p1[xc]*dh0
                     + p0[xc+130]*dl1 + p1[xc+130]*dh1
                     + p0[xc+260]*dl2 + p1[xc+260]*dh2;
            float hi = p2[xc]*dl0 + p3[xc]*dh0
                     + p2[xc+130]*dl1 + p3[xc+130]*dh1
                     + p2[xc+260]*dl2 + p3[xc+260]*dh2;
            l2[xc] = lo; h2[xc] = hi;
        }
    }
    __syncthreads();

    float DL0 = c_DEC_LO[0], DL1 = c_DEC_LO[1], DL2 = c_DEC_LO[2],
          DL3 = c_DEC_LO[3], DL4 = c_DEC_LO[4], DL5 = c_DEC_LO[5];
    float DH0 = c_DEC_HI[0], DH1 = c_DEC_HI[1], DH2 = c_DEC_HI[2],
          DH3 = c_DEC_HI[3], DH4 = c_DEC_HI[4], DH5 = c_DEC_HI[5];
    float* oplane = g_qrgb + ((size_t)bc << 16);
    for (int ml = warp; ml < 16; ml += 8) {
        const float* lrow = sL2 + ml*130;
        const float* hrow = sH2 + ml*130;
        float* orow = oplane + ((m0 + ml) << 8);
        for (int wp = lane; wp < 128; wp += 32) {
            float a  = lrow[wp], b  = lrow[wp+1], cc = lrow[wp+2];
            float ha = hrow[wp], hb = hrow[wp+1], hc = hrow[wp+2];
            float even = a*DL1 + b*DL3 + cc*DL5 + ha*DH1 + hb*DH3 + hc*DH5;
            float odd  = a*DL0 + b*DL2 + cc*DL4 + ha*DH0 + hb*DH2 + hc*DH4;
            *(float2*)(orow + 2*wp) = make_float2(even, odd);
        }
    }
}

// ======== 1x1 conv 64->128: transposed packed weights, LDS.128 broadcasts ========
__global__ __launch_bounds__(256) void conv1x1_k(const float* __restrict__ in,
                                                 const float* __restrict__ w,
                                                 float* __restrict__ out) {
    __shared__ ull swT[64*64];   // [c][o_local] packed; one 64-output half at a time
    int b = blockIdx.y;
    int pb = (blockIdx.x*256 + threadIdx.x)*4;
    const float* ib = in  + (size_t)b*CC*HWN + pb;
    float*       ob = out + (size_t)b*(2*CC)*HWN + pb;

    for (int half = 0; half < 2; half++) {
        for (int i = threadIdx.x; i < 4096; i += 256) {
            int c = i >> 6, o = i & 63;
            float wv = w[half*4096 + o*64 + c];
            swT[i] = pk(wv, wv);
        }
        __syncthreads();
        #pragma unroll 1
        for (int ot = 0; ot < 4; ot++) {
            ull a0[16], a1[16];
            #pragma unroll
            for (int o = 0; o < 16; o++) { a0[o] = 0ULL; a1[o] = 0ULL; }
            #pragma unroll 4
            for (int c = 0; c < 64; c++) {
                float4 x = *(const float4*)(ib + (size_t)c*HWN);
                ull x01 = pk(x.x, x.y), x23 = pk(x.z, x.w);
                const ulonglong2* wr = (const ulonglong2*)(swT + (c << 6) + (ot << 4));
                #pragma unroll
                for (int o2 = 0; o2 < 8; o2++) {
                    ulonglong2 wv = wr[o2];
                    ffma2(a0[2*o2],   wv.x, x01);
                    ffma2(a1[2*o2],   wv.x, x23);
                    ffma2(a0[2*o2+1], wv.y, x01);
                    ffma2(a1[2*o2+1], wv.y, x23);
                }
            }
            #pragma unroll
            for (int o = 0; o < 16; o++) {
                float4 r;
                upk(r.x, r.y, a0[o]);
                upk(r.z, r.w, a1[o]);
                *(float4*)(ob + (size_t)(half*64 + ot*16 + o)*HWN) = r;
            }
        }
        __syncthreads();
    }
}

// ======== depthwise 3x3, shuffle edges, 8 px/thread, rolling rows ========
struct Row8 {
    float4 A, B;
    float pw, nx;
};
__device__ __forceinline__ Row8 load_row8(const float* plane, int y, int lane) {
    Row8 r;
    if (y < 0 || y >= HH) {
        r.A = make_float4(0.f,0.f,0.f,0.f);
        r.B = r.A; r.pw = 0.f; r.nx = 0.f;
        float pw = __shfl_up_sync(0xffffffffu, 0.f, 1);
        float nx = __shfl_down_sync(0xffffffffu, 0.f, 1);
        (void)pw; (void)nx;
        return r;
    }
    const float* p = plane + (y << 8) + (lane << 3);
    r.A = *(const float4*)p;
    r.B = *(const float4*)(p + 4);
    float pw = __shfl_up_sync(0xffffffffu, r.B.w, 1);
    float nx = __shfl_down_sync(0xffffffffu, r.A.x, 1);
    r.pw = (lane == 0)  ? 0.f : pw;
    r.nx = (lane == 31) ? 0.f : nx;
    return r;
}
__device__ __forceinline__ void acc_row8(float* acc, const Row8& r, float wa, float wb, float wc) {
    acc[0] += wa*r.pw  + wb*r.A.x + wc*r.A.y;
    acc[1] += wa*r.A.x + wb*r.A.y + wc*r.A.z;
    acc[2] += wa*r.A.y + wb*r.A.z + wc*r.A.w;
    acc[3] += wa*r.A.z + wb*r.A.w + wc*r.B.x;
    acc[4] += wa*r.A.w + wb*r.B.x + wc*r.B.y;
    acc[5] += wa*r.B.x + wb*r.B.y + wc*r.B.z;
    acc[6] += wa*r.B.y + wb*r.B.z + wc*r.B.w;
    acc[7] += wa*r.B.z + wb*r.B.w + wc*r.nx;
}

__global__ __launch_bounds__(256) void dw3_k(const float* __restrict__ in,
                                             const float* __restrict__ wt,
                                             float* __restrict__ out) {
    int bc = blockIdx.y;
    int c  = bc & 127;
    int warp = threadIdx.x >> 5, lane = threadIdx.x & 31;
    int yb = blockIdx.x*64 + warp*8;

    float w[9];
    #pragma unroll
    for (int k = 0; k < 9; k++) w[k] = wt[c*9 + k];

    const float* plane = in  + ((size_t)bc << 16);
    float*      oplane = out + ((size_t)bc << 16);

    Row8 rp = load_row8(plane, yb - 1, lane);
    Row8 rc = load_row8(plane, yb,     lane);
    #pragma unroll
    for (int i = 0; i < 8; i++) {
        Row8 rn = load_row8(plane, yb + i + 1, lane);
        float acc[8];
        #pragma unroll
        for (int k = 0; k < 8; k++) acc[k] = 0.f;
        acc_row8(acc, rp, w[0], w[1], w[2]);
        acc_row8(acc, rc, w[3], w[4], w[5]);
        acc_row8(acc, rn, w[6], w[7], w[8]);
        float* op = oplane + ((yb + i) << 8) + (lane << 3);
        *(float4*)op       = make_float4(acc[0], acc[1], acc[2], acc[3]);
        *(float4*)(op + 4) = make_float4(acc[4], acc[5], acc[6], acc[7]);
        rp = rc; rc = rn;
    }
}

// ---------- fused Gram reduction: q read once, both modalities ----------
__global__ __launch_bounds__(256, 1) void reduce_qk2_k(const float* __restrict__ q,
                                                       const float* __restrict__ kvr,
                                                       const float* __restrict__ kvd) {
    int chunk = blockIdx.x;
    int bh    = blockIdx.y;
    int b = bh >> 3, h = bh & 7;
    size_t qoff = ((size_t)b*64  + h*8)*HWN;
    size_t koff = ((size_t)b*128 + h*8)*HWN;

    float accr[64], accd[64], qn[8], knr[8], knd[8];
    #pragma unroll
    for (int i = 0; i < 64; i++) { accr[i] = 0.f; accd[i] = 0.f; }
    #pragma unroll
    for (int i = 0; i < 8; i++) { qn[i] = 0.f; knr[i] = 0.f; knd[i] = 0.f; }

    const int CS4 = HWN / NCHUNK / 4;
    int start = chunk * CS4;
    for (int it = threadIdx.x; it < CS4; it += blockDim.x) {
        int idx = start + it;
        float4 qv[8];
        #pragma unroll
        for (int c = 0; c < 8; c++) {
            qv[c] = ((const float4*)(q + qoff + (size_t)c*HWN))[idx];
            qn[c] += qv[c].x*qv[c].x + qv[c].y*qv[c].y + qv[c].z*qv[c].z + qv[c].w*qv[c].w;
        }
        #pragma unroll
        for (int d = 0; d < 8; d++) {
            float4 k4 = ((const float4*)(kvr + koff + (size_t)d*HWN))[idx];
            knr[d] += k4.x*k4.x + k4.y*k4.y + k4.z*k4.z + k4.w*k4.w;
            #pragma unroll
            for (int c = 0; c < 8; c++)
                accr[d*8+c] += qv[c].x*k4.x + qv[c].y*k4.y + qv[c].z*k4.z + qv[c].w*k4.w;
        }
        #pragma unroll
        for (int d = 0; d < 8; d++) {
            float4 k4 = ((const float4*)(kvd + koff + (size_t)d*HWN))[idx];
            knd[d] += k4.x*k4.x + k4.y*k4.y + k4.z*k4.z + k4.w*k4.w;
            #pragma unroll
            for (int c = 0; c < 8; c++)
                accd[d*8+c] += qv[c].x*k4.x + qv[c].y*k4.y + qv[c].z*k4.z + qv[c].w*k4.w;
        }
    }

    __shared__ float sm[8][152];
    int lane = threadIdx.x & 31, warp = threadIdx.x >> 5;
    #pragma unroll
    for (int v = 0; v < 64; v++) {
        float r = accr[v];
        for (int s = 16; s > 0; s >>= 1) r += __shfl_down_sync(0xffffffffu, r, s);
        if (lane == 0) sm[warp][v] = r;
        float r2 = accd[v];
        for (int s = 16; s > 0; s >>= 1) r2 += __shfl_down_sync(0xffffffffu, r2, s);
        if (lane == 0) sm[warp][80+v] = r2;
    }
    #pragma unroll
    for (int v = 0; v < 8; v++) {
        float r = qn[v];
        for (int s = 16; s > 0; s >>= 1) r += __shfl_down_sync(0xffffffffu, r, s);
        if (lane == 0) sm[warp][64+v] = r;
        float r2 = knr[v];
        for (int s = 16; s > 0; s >>= 1) r2 += __shfl_down_sync(0xffffffffu, r2, s);
        if (lane == 0) sm[warp][72+v] = r2;
        float r3 = knd[v];
        for (int s = 16; s > 0; s >>= 1) r3 += __shfl_down_sync(0xffffffffu, r3, s);
        if (lane == 0) sm[warp][144+v] = r3;
    }
    __syncthreads();
    if (threadIdx.x < 160) {
        int which = threadIdx.x / 80;
        int t = threadIdx.x - which*80;
        int col;
        if (which == 0) col = t;
        else            col = (t < 64) ? 80 + t : (t < 72 ? t : 72 + t);
        float s = 0.f;
        #pragma unroll
        for (int wg = 0; wg < 8; wg++) s += sm[wg][col];
        g_part[which][bh][chunk][t] = s;
    }
}

// ---------------- finish reduction + softmax ----------------
__global__ void attn_k(const float* __restrict__ temp) {
    int which = blockIdx.x >> 5;
    int bh    = blockIdx.x & 31;
    int h     = bh & 7;
    __shared__ float sm[80];
    if (threadIdx.x < 80) {
        float s = 0.f;
        #pragma unroll
        for (int ch = 0; ch < NCHUNK; ch++) s += g_part[which][bh][ch][threadIdx.x];
        sm[threadIdx.x] = s;
    }
    __syncthreads();
    if (threadIdx.x < 8) {
        int c = threadIdx.x;
        float t  = temp[h];
        float nq = fmaxf(sqrtf(sm[64+c]), 1e-12f);
        float srow[8];
        #pragma unroll
        for (int d = 0; d < 8; d++) {
            float nk = fmaxf(sqrtf(sm[72+d]), 1e-12f);
            float s = sm[d*8+c] / nk;
            if (which == 0) s /= nq;
            srow[d] = s * t;
        }
        float mx = srow[0];
        #pragma unroll
        for (int d = 1; d < 8; d++) mx = fmaxf(mx, srow[d]);
        float sum = 0.f;
        #pragma unroll
        for (int d = 0; d < 8; d++) { srow[d] = __expf(srow[d]-mx); sum += srow[d]; }
        float inv = 1.f / sum;
        #pragma unroll
        for (int d = 0; d < 8; d++) g_attn[which][bh][c*8+d] = srow[d]*inv;
    }
}

// ---------------- fused epilogue (f32x2, 2 px/thread, LDS.128 pairs) ----------------
__global__ __launch_bounds__(256) void final_k(const float* __restrict__ wproj,
                                               float* __restrict__ out) {
    __shared__ ull sA1t[512], sA2t[512];
    __shared__ ull sW[4096];
    int b = blockIdx.y;
    for (int i = threadIdx.x; i < 512; i += 256) {
        int h = i >> 6, d = (i >> 3) & 7, c = i & 7;
        float a1 = g_attn[0][b*8 + h][c*8 + d];
        float a2 = g_attn[1][b*8 + h][c*8 + d];
        sA1t[i] = pk(a1, a1);
        sA2t[i] = pk(a2, a2);
    }
    for (int i = threadIdx.x; i < 4096; i += 256) {
        float wv = wproj[i];
        sW[i] = pk(wv, wv);
    }
    __syncthreads();

    int n = (blockIdx.x*256 + threadIdx.x)*2;
    const float* vr = g_kvr + ((size_t)b*128 + 64)*HWN + n;
    const float* vd = g_kvd + ((size_t)b*128 + 64)*HWN + n;

    ull p[64];
    #pragma unroll 1
    for (int h = 0; h < 8; h++) {
        ull os[8], oc[8];
        #pragma unroll
        for (int c = 0; c < 8; c++) { os[c] = 0ULL; oc[c] = 0ULL; }
        #pragma unroll
        for (int d = 0; d < 8; d++) {
            float2 r2 = *(const float2*)(vr + (size_t)(h*8+d)*HWN);
            float2 d2 = *(const float2*)(vd + (size_t)(h*8+d)*HWN);
            ull rr = pk(r2.x, r2.y);
            ull dd = pk(d2.x, d2.y);
            const ulonglong2* a1p = (const ulonglong2*)(sA1t + h*64 + d*8);
            const ulonglong2* a2p = (const ulonglong2*)(sA2t + h*64 + d*8);
            #pragma unroll
            for (int c2 = 0; c2 < 4; c2++) {
                ulonglong2 w1 = a1p[c2];
                ffma2(os[2*c2],   w1.x, rr);
                ffma2(os[2*c2+1], w1.y, rr);
                ulonglong2 w2 = a2p[c2];
                ffma2(oc[2*c2],   w2.x, dd);
                ffma2(oc[2*c2+1], w2.y, dd);
            }
        }
        #pragma unroll
        for (int c = 0; c < 8; c++) p[h*8+c] = fmul2(os[c], oc[c]);
    }

    float* ob = out + (size_t)b*64*HWN + n;
    #pragma unroll 4
    for (int o = 0; o < 64; o++) {
        ull acc = 0ULL;
        const ulonglong2* wr = (const ulonglong2*)(sW + o*64);
        #pragma unroll
        for (int c2 = 0; c2 < 32; c2++) {
            ulonglong2 wv = wr[c2];
            ffma2(acc, wv.x, p[2*c2]);
            ffma2(acc, wv.y, p[2*c2+1]);
        }
        float2 r; upk(r.x, r.y, acc);
        *(float2*)(ob + (size_t)o*HWN) = r;
    }
}

// ---------------- host launch ----------------
extern "C" void kernel_launch(void* const* d_in, const int* in_sizes, int n_in,
                              void* d_out, int out_size) {
    const float* rgb   = (const float*)d_in[0];
    const float* depth = (const float*)d_in[1];
    const float* temp  = (const float*)d_in[2];
    const float* wqr   = (const float*)d_in[3];
    const float* wqd   = (const float*)d_in[4];
    const float* wqc   = (const float*)d_in[5];
    const float* w1    = (const float*)d_in[6];
    const float* w5    = (const float*)d_in[7];
    const float* w7    = (const float*)d_in[8];
    const float* w9    = (const float*)d_in[9];
    const float* wproj = (const float*)d_in[10];
    float* out = (float*)d_out;

    void* p;
    cudaGetSymbolAddress(&p, g_qrgb); float* qrg  = (float*)p;
    cudaGetSymbolAddress(&p, g_cvt0); float* cvt0 = (float*)p;
    cudaGetSymbolAddress(&p, g_cvt1); float* cvt1 = (float*)p;
    cudaGetSymbolAddress(&p, g_kvr);  float* kvr  = (float*)p;
    cudaGetSymbolAddress(&p, g_kvd);  float* kvd  = (float*)p;

    static cudaStream_t s1 = 0, s2 = 0;
    static cudaEvent_t evFork1 = 0, evFork2 = 0, evMfe = 0, evDep = 0;
    if (!s1) {
        cudaStreamCreateWithFlags(&s1, cudaStreamNonBlocking);
        cudaStreamCreateWithFlags(&s2, cudaStreamNonBlocking);
        cudaEventCreateWithFlags(&evFork1, cudaEventDisableTiming);
        cudaEventCreateWithFlags(&evFork2, cudaEventDisableTiming);
        cudaEventCreateWithFlags(&evMfe,  cudaEventDisableTiming);
        cudaEventCreateWithFlags(&evDep,  cudaEventDisableTiming);
    }

    const int T = 256;
    const int MFE_BACK_SMEM = (4*RAW_SB + 4*POST_SB) * 4;   // 46528 B
    cudaFuncSetAttribute(mfe_back_k, cudaFuncAttributeMaxDynamicSharedMemorySize, MFE_BACK_SMEM);

    // fork: main(0) -> s1 (mfe), s2 (depth chain)
    cudaEventRecord(evFork1, 0);
    cudaStreamWaitEvent(s1, evFork1, 0);
    cudaEventRecord(evFork2, 0);
    cudaStreamWaitEvent(s2, evFork2, 0);

    dim3 cg(HWN/(T*4), BB);
    dim3 dg(4, BB*128);

    // ---- branch s2: depth conv -> dw3 ----
    conv1x1_k<<<cg, T, 0, s2>>>(depth, wqd, cvt1);
    dw3_k<<<dg, T, 0, s2>>>(cvt1, wqc, kvd);
    cudaEventRecord(evDep, s2);

    // ---- branch s1: MFE ----
    dim3 fgk(9, BB*CC);
    mfe_front_k<<<fgk, T, 0, s1>>>(rgb);
    dim3 bgk(16, BB*CC);
    mfe_back_k<<<bgk, T, MFE_BACK_SMEM, s1>>>(w1, w5, w7, w9);
    cudaEventRecord(evMfe, s1);

    // ---- main stream: rgb conv -> dw3 ----
    conv1x1_k<<<cg, T>>>(rgb, wqr, cvt0);
    dw3_k<<<dg, T>>>(cvt0, wqc, kvr);

    // join both branches into main stream
    cudaStreamWaitEvent(0, evMfe, 0);
    cudaStreamWaitEvent(0, evDep, 0);

    // ---- attention statistics ----
    dim3 rg(NCHUNK, 32);
    reduce_qk2_k<<<rg, T>>>(qrg, kvr, kvd);
    attn_k<<<64, 128>>>(temp);

    // ---- fused epilogue ----
    dim3 fg(HWN/(T*2), BB);
    final_k<<<fg, T>>>(wproj, out);
}